// round 8
// baseline (speedup 1.0000x reference)
#include <cuda_runtime.h>
#include <cuda_bf16.h>
#include <math.h>

#define NOP     2048
#define NGATES  8192
#define NACT    1024
#define NB      32

#define SMEM_ROWS 54
// dynamic smem layout (bytes)
#define OFF_W    0
#define OFF_H    (SMEM_ROWS * NOP * 2)          // 221184 (h packed bf16x2: 4KB)
#define OFF_PART (OFF_H + 1024 * 4)             // 225280 (part[4][64] f32)
#define OFF_XG   (OFF_PART + 4 * 64 * 4)        // 226304
#define SMEM_TOTAL (OFF_XG + 64 * 4)            // 226560 <= 232448

// ---------------- scratch (static device globals) ---------------------------
__device__ __align__(16) __nv_bfloat16 g_whh[(size_t)NGATES * NOP]; // 32 MB bf16
__device__ __align__(16) float g_xg[NGATES];
__device__ __align__(16) __nv_bfloat16 g_hb[2][NOP];   // h exchange, packed bf16
__device__ __align__(16) float g_hall[(size_t)NACT * NOP];
__device__ __align__(16) float g_ent[NACT];
__device__ __align__(16) float g_rein[NACT];
// barrier: one counting atomic + 8 flag replicas on separate 128B lines.
// g_cnt returns to 0 each barrier; flags reset by detect_act -> graph-safe.
__device__ unsigned g_cnt = 0;
__device__ __align__(128) unsigned g_flags[256];   // replicas at i*32
__device__ int g_act64 = 0;

// ---------------- helpers ---------------------------------------------------
__device__ __forceinline__ float uaf(unsigned u) { return __uint_as_float(u); }

__device__ __forceinline__ float tanh_fast(float x) {
    float y;
    asm("tanh.approx.f32 %0, %1;" : "=f"(y) : "f"(x));
    return y;
}
__device__ __forceinline__ float sigmoid_fast(float x) {
    return 0.5f * tanh_fast(0.5f * x) + 0.5f;
}

__device__ __forceinline__ unsigned hfma2(unsigned a, unsigned b, unsigned c) {
    unsigned d;
    asm("fma.rn.bf16x2 %0, %1, %2, %3;" : "=r"(d) : "r"(a), "r"(b), "r"(c));
    return d;
}

__device__ __forceinline__ void st_release(unsigned* p, unsigned v) {
    asm volatile("st.release.gpu.global.u32 [%0], %1;" :: "l"(p), "r"(v) : "memory");
}
__device__ __forceinline__ unsigned ld_acquire(const unsigned* p) {
    unsigned v;
    asm volatile("ld.acquire.gpu.global.u32 %0, [%1];" : "=r"(v) : "l"(p) : "memory");
    return v;
}

// arrive: acq_rel RMW; if last, reset count and release all 8 flag replicas.
// Returns 1 iff this thread released the barrier (it may then skip polling).
__device__ __forceinline__ unsigned bar_arrive(unsigned ns) {
    unsigned a;
    asm volatile("atom.acq_rel.gpu.global.add.u32 %0, [%1], %2;"
                 : "=r"(a) : "l"(&g_cnt), "r"(1u) : "memory");
    if (a == gridDim.x - 1) {
        asm volatile("st.relaxed.gpu.global.u32 [%0], %1;"
                     :: "l"(&g_cnt), "r"(0u) : "memory");
#pragma unroll
        for (int i = 0; i < 8; i++) st_release(&g_flags[i * 32], ns);
        return 1u;
    }
    return 0u;
}

// quarter-row dot: 512 K-values. wa/wb = 16 packed bf16 pairs, hr = 8 packed
// bf16x2 of h. Two 4-deep bf16x2 FMA chains, then exact unpack to f32.
__device__ __forceinline__ float dotq(uint4 wa, uint4 wb,
                                      const unsigned* __restrict__ hr) {
    unsigned a0 = 0u, a1 = 0u;
    a0 = hfma2(wa.x, hr[0], a0);
    a1 = hfma2(wb.x, hr[4], a1);
    a0 = hfma2(wa.y, hr[1], a0);
    a1 = hfma2(wb.y, hr[5], a1);
    a0 = hfma2(wa.z, hr[2], a0);
    a1 = hfma2(wb.z, hr[6], a1);
    a0 = hfma2(wa.w, hr[3], a0);
    a1 = hfma2(wb.w, hr[7], a1);
    return (uaf(a0 << 16) + uaf(a0 & 0xffff0000u))
         + (uaf(a1 << 16) + uaf(a1 & 0xffff0000u));
}

// ---------------- action dtype detect + barrier reset ------------------------
__global__ void detect_act(const int* __restrict__ act_words) {
    __shared__ int any;
    if (threadIdx.x == 0) { any = 0; g_cnt = 0; }
    g_flags[threadIdx.x] = 0;   // 256 threads cover all replica lines
    __syncthreads();
    for (int i = 1 + 2 * threadIdx.x; i < 512; i += 2 * blockDim.x)
        if (act_words[i] != 0) atomicOr(&any, 1);
    __syncthreads();
    if (threadIdx.x == 0) g_act64 = (any == 0) ? 1 : 0;
}

// ---------------- prep: W_hh fp32 -> bf16 (lo=even k, hi=odd k) --------------
__global__ void prep_w(const float* __restrict__ Whh) {
    const int n = NGATES * NOP / 4;
    for (int i = blockIdx.x * blockDim.x + threadIdx.x; i < n;
         i += gridDim.x * blockDim.x) {
        float4 v = reinterpret_cast<const float4*>(Whh)[i];
        unsigned lo = ((unsigned)__bfloat16_as_ushort(__float2bfloat16(v.y)) << 16) |
                       (unsigned)__bfloat16_as_ushort(__float2bfloat16(v.x));
        unsigned hi = ((unsigned)__bfloat16_as_ushort(__float2bfloat16(v.w)) << 16) |
                       (unsigned)__bfloat16_as_ushort(__float2bfloat16(v.z));
        reinterpret_cast<uint2*>(g_whh)[i] = make_uint2(lo, hi);
    }
}

// ---------------- prep: x_gates ----------------------------------------------
__global__ void prep_xg(const float* __restrict__ Wih,
                        const float* __restrict__ bih,
                        const float* __restrict__ bhh) {
    int warp = (blockIdx.x * blockDim.x + threadIdx.x) >> 5;
    int lane = threadIdx.x & 31;
    if (warp >= NGATES) return;
    const float4* rp = reinterpret_cast<const float4*>(Wih + (size_t)warp * NOP);
    float s = 0.f;
    for (int m = lane; m < NOP / 4; m += 32) {
        float4 v = rp[m];
        s += (v.x + v.y) + (v.z + v.w);
    }
#pragma unroll
    for (int o = 16; o; o >>= 1) s += __shfl_xor_sync(0xffffffffu, s, o);
    if (lane == 0) g_xg[warp] = s * (1.0f / NOP) + bih[warp] + bhh[warp];
}

// ---------------- main persistent LSTM kernel -------------------------------
__global__ void __launch_bounds__(1024, 1) lstm_main() {
    extern __shared__ unsigned char smem[];
    __nv_bfloat16* w_s = reinterpret_cast<__nv_bfloat16*>(smem + OFF_W);
    unsigned* h_s  = reinterpret_cast<unsigned*>(smem + OFF_H);  // 1024 bf16x2
    float* part = reinterpret_cast<float*>(smem + OFF_PART);     // [4][64]
    float* xg_s = reinterpret_cast<float*>(smem + OFF_XG);       // [64]

    const int tid  = threadIdx.x;
    const int lane = tid & 31;
    const int wid  = tid >> 5;           // 0..31
    const int qtr  = wid >> 3;           // K-quarter 0..3
    const int ww   = wid & 7;            // warp within quarter

    const int nblk = gridDim.x;
    const int b    = blockIdx.x;
    const int q    = NOP / nblk, r = NOP % nblk;
    const int base = b * q + (b < r ? b : r);
    const int cnt  = q + (b < r ? 1 : 0);          // <= 14 for >=147 blocks
    const int nrows = 4 * cnt;                      // <= 56
    const int nsm   = nrows < SMEM_ROWS ? nrows : SMEM_ROWS;

    // ---- stage weight slice into smem (rows [0, nsm)) ----
    for (int l = wid; l < nsm; l += 32) {
        int j = (l / cnt) * NOP + base + (l % cnt);
        const uint4* src = reinterpret_cast<const uint4*>(g_whh + (size_t)j * NOP);
        uint4* dst = reinterpret_cast<uint4*>(w_s + (size_t)l * NOP);
        for (int m = lane; m < 256; m += 32) dst[m] = src[m];
    }
    for (int l = tid; l < nrows; l += blockDim.x) {
        int j = (l / cnt) * NOP + base + (l % cnt);
        xg_s[l] = g_xg[j];
    }

    // ---- tail row (i=6): l6 = 48+ww; registers if it spills smem ----
    const int l6 = 48 + ww;
    const bool tail_act = l6 < nrows;
    const bool tail_reg = tail_act && (l6 >= nsm);
    uint4 wra = {0,0,0,0}, wrb = {0,0,0,0};
    if (tail_reg) {
        int j = (l6 / cnt) * NOP + base + (l6 % cnt);
        const uint4* wq = reinterpret_cast<const uint4*>(g_whh + (size_t)j * NOP)
                          + qtr * 64;
        wra = wq[lane]; wrb = wq[32 + lane];
    }

    // ---- publish h(0) = 0 (packed bf16), arrive barrier 0 ----
    float c_reg = 0.f, h_reg = 0.f;     // warp0, lane < cnt
    unsigned my_rel = 0;                 // thread 0 only: did I release?
    if (wid == 0) {
        if (lane < cnt) {
            unsigned short z = 0;
            asm volatile("st.global.cg.u16 [%0], %1;"
                         :: "l"(&g_hb[0][base + lane]), "h"(z) : "memory");
        }
        __syncwarp();
        if (lane == 0) my_rel = bar_arrive(1u);
    }

    const unsigned* my_flag = &g_flags[(b & 7) * 32];
    int cur = 0;

    for (int t = 0; t < NACT; ++t) {
        // previous step's output store hides in the wait window
        if (wid == 0 && lane < cnt && t > 0)
            g_hall[(size_t)(t - 1) * NOP + base + lane] = h_reg;

        const unsigned tgt = (unsigned)(t + 1);
        if (tid == 0) {
            if (!my_rel) {
                while (ld_acquire(my_flag) < tgt) { }
            }
            my_rel = 0;
        }
        __syncthreads();

        // ---- stage h(t): already bf16-packed; raw 16B copy L2 -> smem ----
        if (tid < 256) {
            uint4 v = __ldcg(reinterpret_cast<const uint4*>(g_hb[cur]) + tid);
            reinterpret_cast<uint4*>(h_s)[tid] = v;
        }
        __syncthreads();

        // ---- per-lane packed h chunk: 16 K-values of this quarter ----
        unsigned hr[8];
        {
            const uint4* hp = reinterpret_cast<const uint4*>(h_s);
            uint4 h0 = hp[qtr * 64 + lane];        // k = qtr*512 + lane*8 ..
            uint4 h1 = hp[qtr * 64 + 32 + lane];   // k = qtr*512+256+lane*8 ..
            hr[0] = h0.x; hr[1] = h0.y; hr[2] = h0.z; hr[3] = h0.w;
            hr[4] = h1.x; hr[5] = h1.y; hr[6] = h1.z; hr[7] = h1.w;
        }

        // ---- 6 uniform smem rows + 1 tail row (quarter-dots) ----
        float s[7];
        const uint4* wbase = reinterpret_cast<const uint4*>(w_s) + qtr * 64 + lane;
#pragma unroll
        for (int i = 0; i < 6; i++) {
            const uint4* wp = wbase + (size_t)(ww + 8 * i) * 128;
            s[i] = dotq(wp[0], wp[32], hr);
        }
        if (tail_act) {
            if (tail_reg) {
                s[6] = dotq(wra, wrb, hr);
            } else {
                const uint4* wp = wbase + (size_t)l6 * 128;
                s[6] = dotq(wp[0], wp[32], hr);
            }
        } else s[6] = 0.f;

        // interleaved cross-lane reduction: 7 parallel shfl chains
#pragma unroll
        for (int o = 16; o; o >>= 1) {
#pragma unroll
            for (int i = 0; i < 7; i++)
                s[i] += __shfl_xor_sync(0xffffffffu, s[i], o);
        }
        if (lane == 0) {
#pragma unroll
            for (int i = 0; i < 7; i++) {
                int l = ww + 8 * i;
                if (l < nrows) part[qtr * 64 + l] = s[i];
            }
        }
        __syncthreads();

        // ---- cell update (warp 0), publish packed h(t+1), arrive ----
        if (wid == 0) {
            if (lane < cnt) {
                float gv[4];
#pragma unroll
                for (int g = 0; g < 4; ++g) {
                    int l = g * cnt + lane;
                    gv[g] = (part[l] + part[64 + l])
                          + (part[128 + l] + part[192 + l]) + xg_s[l];
                }
                float ii = sigmoid_fast(gv[0]);
                float ff = sigmoid_fast(gv[1]);
                float gg = tanh_fast(gv[2]);
                float oo = sigmoid_fast(gv[3]);
                c_reg = ff * c_reg + ii * gg;
                h_reg = oo * tanh_fast(c_reg);
                if (t + 1 < NACT) {
                    unsigned short hb =
                        __bfloat16_as_ushort(__float2bfloat16(h_reg));
                    asm volatile("st.global.cg.u16 [%0], %1;"
                                 :: "l"(&g_hb[cur ^ 1][base + lane]), "h"(hb)
                                 : "memory");
                }
            }
            __syncwarp();
            if (lane == 0 && t + 1 < NACT)
                my_rel = bar_arrive((unsigned)(t + 2));
        }
        cur ^= 1;
    }

    // final output row
    if (wid == 0 && lane < cnt)
        g_hall[(size_t)(NACT - 1) * NOP + base + lane] = h_reg;
}

// ---------------- epilogue ----------------------------------------------------
__global__ void post_rows(const int* __restrict__ act_words,
                          const float* __restrict__ rewards) {
    __shared__ float row[NOP];
    __shared__ float red[256];
    const int t = blockIdx.x, tid = threadIdx.x;
    const float* src = g_hall + (size_t)t * NOP;
    for (int i = tid; i < NOP; i += 256) row[i] = src[i];
    __syncthreads();

    float m = -1e30f;
    for (int i = tid; i < NOP; i += 256) m = fmaxf(m, row[i]);
    red[tid] = m; __syncthreads();
    for (int s = 128; s; s >>= 1) {
        if (tid < s) red[tid] = fmaxf(red[tid], red[tid + s]);
        __syncthreads();
    }
    m = red[0]; __syncthreads();

    float se = 0.f, sx = 0.f;
    for (int i = tid; i < NOP; i += 256) {
        float x = row[i];
        float e = expf(x - m);
        se += e; sx += e * x;
    }
    red[tid] = se; __syncthreads();
    for (int s = 128; s; s >>= 1) {
        if (tid < s) red[tid] += red[tid + s];
        __syncthreads();
    }
    const float SE = red[0]; __syncthreads();
    red[tid] = sx; __syncthreads();
    for (int s = 128; s; s >>= 1) {
        if (tid < s) red[tid] += red[tid + s];
        __syncthreads();
    }
    const float SX = red[0]; __syncthreads();

    const float lse = m + logf(SE);
    if (tid == 0) g_ent[t] = lse - SX / SE;

    if (tid < 32) {
        int flat = tid * NACT + t;
        int a = g_act64 ? act_words[2 * flat] : act_words[flat];
        a = a < 0 ? 0 : (a >= NOP ? NOP - 1 : a);
        float lp = row[a] - lse;
        float pr = rewards[tid] * lp;
#pragma unroll
        for (int o = 16; o; o >>= 1) pr += __shfl_xor_sync(0xffffffffu, pr, o);
        if (tid == 0) g_rein[t] = pr;
    }
}

__global__ void post_final(float* __restrict__ out) {
    __shared__ float r1[256], r2[256];
    const int tid = threadIdx.x;
    float se = 0.f, sr = 0.f;
    for (int i = tid; i < NACT; i += 256) { se += g_ent[i]; sr += g_rein[i]; }
    r1[tid] = se; r2[tid] = sr; __syncthreads();
    for (int s = 128; s; s >>= 1) {
        if (tid < s) { r1[tid] += r1[tid + s]; r2[tid] += r2[tid + s]; }
        __syncthreads();
    }
    if (tid == 0) out[0] = (-r2[0] + (float)NB * r1[0]) / (float)NB;
}

// ---------------- launch -------------------------------------------------------
extern "C" void kernel_launch(void* const* d_in, const int* in_sizes, int n_in,
                              void* d_out, int out_size) {
    const float* Wih     = (const float*)d_in[0];
    const float* Whh     = (const float*)d_in[1];
    const float* bih     = (const float*)d_in[2];
    const float* bhh     = (const float*)d_in[3];
    const float* rewards = (const float*)d_in[4];
    const int*   actw    = (const int*)d_in[5];
    float* out = (float*)d_out;

    int dev = 0;
    cudaGetDevice(&dev);
    int sms = 148;
    cudaDeviceGetAttribute(&sms, cudaDevAttrMultiProcessorCount, dev);
    if (sms < 147) sms = 148;   // need cnt <= 14 (54 smem rows + 2 reg rows)
    if (sms > 256) sms = 256;
    cudaFuncSetAttribute(lstm_main, cudaFuncAttributeMaxDynamicSharedMemorySize,
                         SMEM_TOTAL);

    detect_act<<<1, 256>>>(actw);
    prep_w<<<2048, 256>>>(Whh);
    prep_xg<<<1024, 256>>>(Wih, bih, bhh);
    lstm_main<<<sms, 1024, SMEM_TOTAL>>>();
    post_rows<<<NACT, 256>>>(actw, rewards);
    post_final<<<1, 256>>>(out);
}

// round 9
// speedup vs baseline: 1.8746x; 1.8746x over previous
#include <cuda_runtime.h>
#include <cuda_bf16.h>
#include <math.h>

#define NOP     2048
#define NGATES  8192
#define NACT    1024
#define NB      32

#define SMEM_ROWS 54
// dynamic smem layout (bytes)
#define OFF_W    0
#define OFF_H    (SMEM_ROWS * NOP * 2)          // 221184 (h packed bf16x2: 4KB)
#define OFF_PART (OFF_H + 1024 * 4)             // 225280 (part[4][64] f32)
#define OFF_XG   (OFF_PART + 4 * 64 * 4)        // 226304
#define SMEM_TOTAL (OFF_XG + 64 * 4)            // 226560 <= 232448

// ---------------- scratch (static device globals) ---------------------------
__device__ __align__(16) __nv_bfloat16 g_whh[(size_t)NGATES * NOP]; // 32 MB bf16
__device__ __align__(16) float g_xg[NGATES];
__device__ __align__(16) float g_h[2][NOP];
__device__ __align__(16) float g_hall[(size_t)NACT * NOP];
__device__ __align__(16) float g_ent[NACT];
__device__ __align__(16) float g_rein[NACT];
// single monotonic arrival counter. Arrive = red.release (no return trip);
// wait = poll counter >= nblk*(t+1). Reset by detect_act -> graph-safe.
__device__ unsigned g_cnt = 0;
__device__ int g_act64 = 0;

// ---------------- helpers ---------------------------------------------------
__device__ __forceinline__ float uaf(unsigned u) { return __uint_as_float(u); }

__device__ __forceinline__ float tanh_fast(float x) {
    float y;
    asm("tanh.approx.f32 %0, %1;" : "=f"(y) : "f"(x));
    return y;
}
__device__ __forceinline__ float sigmoid_fast(float x) {
    return 0.5f * tanh_fast(0.5f * x) + 0.5f;
}

__device__ __forceinline__ unsigned hfma2(unsigned a, unsigned b, unsigned c) {
    unsigned d;
    asm("fma.rn.bf16x2 %0, %1, %2, %3;" : "=r"(d) : "r"(a), "r"(b), "r"(c));
    return d;
}

// fire-and-forget arrival: release orders this block's prior h stores.
__device__ __forceinline__ void bar_arrive_red() {
    asm volatile("red.release.gpu.global.add.u32 [%0], %1;"
                 :: "l"(&g_cnt), "r"(1u) : "memory");
}
__device__ __forceinline__ unsigned ld_acquire(const unsigned* p) {
    unsigned v;
    asm volatile("ld.acquire.gpu.global.u32 %0, [%1];" : "=r"(v) : "l"(p) : "memory");
    return v;
}

// quarter-row dot: 512 K-values. wa/wb = 16 packed bf16 pairs, hr = 8 packed
// bf16x2 of h. Two 4-deep bf16x2 FMA chains, then exact unpack to f32.
__device__ __forceinline__ float dotq(uint4 wa, uint4 wb,
                                      const unsigned* __restrict__ hr) {
    unsigned a0 = 0u, a1 = 0u;
    a0 = hfma2(wa.x, hr[0], a0);
    a1 = hfma2(wb.x, hr[4], a1);
    a0 = hfma2(wa.y, hr[1], a0);
    a1 = hfma2(wb.y, hr[5], a1);
    a0 = hfma2(wa.z, hr[2], a0);
    a1 = hfma2(wb.z, hr[6], a1);
    a0 = hfma2(wa.w, hr[3], a0);
    a1 = hfma2(wb.w, hr[7], a1);
    return (uaf(a0 << 16) + uaf(a0 & 0xffff0000u))
         + (uaf(a1 << 16) + uaf(a1 & 0xffff0000u));
}

// ---------------- action dtype detect + barrier reset ------------------------
__global__ void detect_act(const int* __restrict__ act_words) {
    __shared__ int any;
    if (threadIdx.x == 0) { any = 0; g_cnt = 0; }
    __syncthreads();
    for (int i = 1 + 2 * threadIdx.x; i < 512; i += 2 * blockDim.x)
        if (act_words[i] != 0) atomicOr(&any, 1);
    __syncthreads();
    if (threadIdx.x == 0) g_act64 = (any == 0) ? 1 : 0;
}

// ---------------- prep: W_hh fp32 -> bf16 (lo=even k, hi=odd k) --------------
__global__ void prep_w(const float* __restrict__ Whh) {
    const int n = NGATES * NOP / 4;
    for (int i = blockIdx.x * blockDim.x + threadIdx.x; i < n;
         i += gridDim.x * blockDim.x) {
        float4 v = reinterpret_cast<const float4*>(Whh)[i];
        unsigned lo = ((unsigned)__bfloat16_as_ushort(__float2bfloat16(v.y)) << 16) |
                       (unsigned)__bfloat16_as_ushort(__float2bfloat16(v.x));
        unsigned hi = ((unsigned)__bfloat16_as_ushort(__float2bfloat16(v.w)) << 16) |
                       (unsigned)__bfloat16_as_ushort(__float2bfloat16(v.z));
        reinterpret_cast<uint2*>(g_whh)[i] = make_uint2(lo, hi);
    }
}

// ---------------- prep: x_gates ----------------------------------------------
__global__ void prep_xg(const float* __restrict__ Wih,
                        const float* __restrict__ bih,
                        const float* __restrict__ bhh) {
    int warp = (blockIdx.x * blockDim.x + threadIdx.x) >> 5;
    int lane = threadIdx.x & 31;
    if (warp >= NGATES) return;
    const float4* rp = reinterpret_cast<const float4*>(Wih + (size_t)warp * NOP);
    float s = 0.f;
    for (int m = lane; m < NOP / 4; m += 32) {
        float4 v = rp[m];
        s += (v.x + v.y) + (v.z + v.w);
    }
#pragma unroll
    for (int o = 16; o; o >>= 1) s += __shfl_xor_sync(0xffffffffu, s, o);
    if (lane == 0) g_xg[warp] = s * (1.0f / NOP) + bih[warp] + bhh[warp];
}

// ---------------- main persistent LSTM kernel -------------------------------
__global__ void __launch_bounds__(1024, 1) lstm_main() {
    extern __shared__ unsigned char smem[];
    __nv_bfloat16* w_s = reinterpret_cast<__nv_bfloat16*>(smem + OFF_W);
    unsigned* h_s  = reinterpret_cast<unsigned*>(smem + OFF_H);  // 1024 bf16x2
    float* part = reinterpret_cast<float*>(smem + OFF_PART);     // [4][64]
    float* xg_s = reinterpret_cast<float*>(smem + OFF_XG);       // [64]

    const int tid  = threadIdx.x;
    const int lane = tid & 31;
    const int wid  = tid >> 5;           // 0..31
    const int qtr  = wid >> 3;           // K-quarter 0..3
    const int ww   = wid & 7;            // warp within quarter

    const int nblk = gridDim.x;
    const int b    = blockIdx.x;
    const int q    = NOP / nblk, r = NOP % nblk;
    const int base = b * q + (b < r ? b : r);
    const int cnt  = q + (b < r ? 1 : 0);          // <= 14 for >=147 blocks
    const int nrows = 4 * cnt;                      // <= 56
    const int nsm   = nrows < SMEM_ROWS ? nrows : SMEM_ROWS;

    // ---- stage weight slice into smem (rows [0, nsm)) ----
    for (int l = wid; l < nsm; l += 32) {
        int j = (l / cnt) * NOP + base + (l % cnt);
        const uint4* src = reinterpret_cast<const uint4*>(g_whh + (size_t)j * NOP);
        uint4* dst = reinterpret_cast<uint4*>(w_s + (size_t)l * NOP);
        for (int m = lane; m < 256; m += 32) dst[m] = src[m];
    }
    for (int l = tid; l < nrows; l += blockDim.x) {
        int j = (l / cnt) * NOP + base + (l % cnt);
        xg_s[l] = g_xg[j];
    }

    // ---- tail row (i=6): l6 = 48+ww; registers if it spills smem ----
    const int l6 = 48 + ww;
    const bool tail_act = l6 < nrows;
    const bool tail_reg = tail_act && (l6 >= nsm);
    uint4 wra = {0,0,0,0}, wrb = {0,0,0,0};
    if (tail_reg) {
        int j = (l6 / cnt) * NOP + base + (l6 % cnt);
        const uint4* wq = reinterpret_cast<const uint4*>(g_whh + (size_t)j * NOP)
                          + qtr * 64;
        wra = wq[lane]; wrb = wq[32 + lane];
    }

    // ---- publish h(0) = 0, arrive (red.release, no return trip) ----
    float c_reg = 0.f, h_reg = 0.f;     // warp0, lane < cnt
    if (wid == 0) {
        if (lane < cnt) __stcg(&g_h[0][base + lane], 0.f);
        __syncwarp();
        if (lane == 0) bar_arrive_red();
    }

    int cur = 0;

    for (int t = 0; t < NACT; ++t) {
        // previous step's output store hides in the wait window
        if (wid == 0 && lane < cnt && t > 0)
            g_hall[(size_t)(t - 1) * NOP + base + lane] = h_reg;

        // ---- wait: counter reaches nblk*(t+1) (arrivals through step t) ----
        if (tid == 0) {
            const unsigned tgt = (unsigned)nblk * (unsigned)(t + 1);
            while (ld_acquire(&g_cnt) < tgt) { }
        }
        __syncthreads();

        // ---- stage h(t): load f32 from L2, pack to bf16x2 in smem ----
        if (tid < 512) {
            float4 v = __ldcg(reinterpret_cast<const float4*>(g_h[cur]) + tid);
            __nv_bfloat162 p0 = __floats2bfloat162_rn(v.x, v.y);  // .x = low half
            __nv_bfloat162 p1 = __floats2bfloat162_rn(v.z, v.w);
            uint2 st;
            st.x = *reinterpret_cast<unsigned*>(&p0);
            st.y = *reinterpret_cast<unsigned*>(&p1);
            reinterpret_cast<uint2*>(h_s)[tid] = st;
        }
        __syncthreads();

        // ---- per-lane packed h chunk: 16 K-values of this quarter ----
        unsigned hr[8];
        {
            const uint4* hp = reinterpret_cast<const uint4*>(h_s);
            uint4 h0 = hp[qtr * 64 + lane];        // k = qtr*512 + lane*8 ..
            uint4 h1 = hp[qtr * 64 + 32 + lane];   // k = qtr*512+256+lane*8 ..
            hr[0] = h0.x; hr[1] = h0.y; hr[2] = h0.z; hr[3] = h0.w;
            hr[4] = h1.x; hr[5] = h1.y; hr[6] = h1.z; hr[7] = h1.w;
        }

        // ---- 6 uniform smem rows + 1 tail row (quarter-dots) ----
        float s[7];
        const uint4* wbase = reinterpret_cast<const uint4*>(w_s) + qtr * 64 + lane;
#pragma unroll
        for (int i = 0; i < 6; i++) {
            const uint4* wp = wbase + (size_t)(ww + 8 * i) * 128;
            s[i] = dotq(wp[0], wp[32], hr);
        }
        if (tail_act) {
            if (tail_reg) {
                s[6] = dotq(wra, wrb, hr);
            } else {
                const uint4* wp = wbase + (size_t)l6 * 128;
                s[6] = dotq(wp[0], wp[32], hr);
            }
        } else s[6] = 0.f;

        // interleaved cross-lane reduction: 7 parallel shfl chains
#pragma unroll
        for (int o = 16; o; o >>= 1) {
#pragma unroll
            for (int i = 0; i < 7; i++)
                s[i] += __shfl_xor_sync(0xffffffffu, s[i], o);
        }
        if (lane == 0) {
#pragma unroll
            for (int i = 0; i < 7; i++) {
                int l = ww + 8 * i;
                if (l < nrows) part[qtr * 64 + l] = s[i];
            }
        }
        __syncthreads();

        // ---- cell update (warp 0), publish h(t+1), arrive ----
        if (wid == 0) {
            if (lane < cnt) {
                float gv[4];
#pragma unroll
                for (int g = 0; g < 4; ++g) {
                    int l = g * cnt + lane;
                    gv[g] = (part[l] + part[64 + l])
                          + (part[128 + l] + part[192 + l]) + xg_s[l];
                }
                float ii = sigmoid_fast(gv[0]);
                float ff = sigmoid_fast(gv[1]);
                float gg = tanh_fast(gv[2]);
                float oo = sigmoid_fast(gv[3]);
                c_reg = ff * c_reg + ii * gg;
                h_reg = oo * tanh_fast(c_reg);
                if (t + 1 < NACT) __stcg(&g_h[cur ^ 1][base + lane], h_reg);
            }
            __syncwarp();
            if (lane == 0 && t + 1 < NACT) bar_arrive_red();
        }
        cur ^= 1;
    }

    // final output row
    if (wid == 0 && lane < cnt)
        g_hall[(size_t)(NACT - 1) * NOP + base + lane] = h_reg;
}

// ---------------- epilogue ----------------------------------------------------
__global__ void post_rows(const int* __restrict__ act_words,
                          const float* __restrict__ rewards) {
    __shared__ float row[NOP];
    __shared__ float red[256];
    const int t = blockIdx.x, tid = threadIdx.x;
    const float* src = g_hall + (size_t)t * NOP;
    for (int i = tid; i < NOP; i += 256) row[i] = src[i];
    __syncthreads();

    float m = -1e30f;
    for (int i = tid; i < NOP; i += 256) m = fmaxf(m, row[i]);
    red[tid] = m; __syncthreads();
    for (int s = 128; s; s >>= 1) {
        if (tid < s) red[tid] = fmaxf(red[tid], red[tid + s]);
        __syncthreads();
    }
    m = red[0]; __syncthreads();

    float se = 0.f, sx = 0.f;
    for (int i = tid; i < NOP; i += 256) {
        float x = row[i];
        float e = expf(x - m);
        se += e; sx += e * x;
    }
    red[tid] = se; __syncthreads();
    for (int s = 128; s; s >>= 1) {
        if (tid < s) red[tid] += red[tid + s];
        __syncthreads();
    }
    const float SE = red[0]; __syncthreads();
    red[tid] = sx; __syncthreads();
    for (int s = 128; s; s >>= 1) {
        if (tid < s) red[tid] += red[tid + s];
        __syncthreads();
    }
    const float SX = red[0]; __syncthreads();

    const float lse = m + logf(SE);
    if (tid == 0) g_ent[t] = lse - SX / SE;

    if (tid < 32) {
        int flat = tid * NACT + t;
        int a = g_act64 ? act_words[2 * flat] : act_words[flat];
        a = a < 0 ? 0 : (a >= NOP ? NOP - 1 : a);
        float lp = row[a] - lse;
        float pr = rewards[tid] * lp;
#pragma unroll
        for (int o = 16; o; o >>= 1) pr += __shfl_xor_sync(0xffffffffu, pr, o);
        if (tid == 0) g_rein[t] = pr;
    }
}

__global__ void post_final(float* __restrict__ out) {
    __shared__ float r1[256], r2[256];
    const int tid = threadIdx.x;
    float se = 0.f, sr = 0.f;
    for (int i = tid; i < NACT; i += 256) { se += g_ent[i]; sr += g_rein[i]; }
    r1[tid] = se; r2[tid] = sr; __syncthreads();
    for (int s = 128; s; s >>= 1) {
        if (tid < s) { r1[tid] += r1[tid + s]; r2[tid] += r2[tid + s]; }
        __syncthreads();
    }
    if (tid == 0) out[0] = (-r2[0] + (float)NB * r1[0]) / (float)NB;
}

// ---------------- launch -------------------------------------------------------
extern "C" void kernel_launch(void* const* d_in, const int* in_sizes, int n_in,
                              void* d_out, int out_size) {
    const float* Wih     = (const float*)d_in[0];
    const float* Whh     = (const float*)d_in[1];
    const float* bih     = (const float*)d_in[2];
    const float* bhh     = (const float*)d_in[3];
    const float* rewards = (const float*)d_in[4];
    const int*   actw    = (const int*)d_in[5];
    float* out = (float*)d_out;

    int dev = 0;
    cudaGetDevice(&dev);
    int sms = 148;
    cudaDeviceGetAttribute(&sms, cudaDevAttrMultiProcessorCount, dev);
    if (sms < 147) sms = 148;   // need cnt <= 14 (54 smem rows + 2 reg rows)
    cudaFuncSetAttribute(lstm_main, cudaFuncAttributeMaxDynamicSharedMemorySize,
                         SMEM_TOTAL);

    detect_act<<<1, 256>>>(actw);
    prep_w<<<2048, 256>>>(Whh);
    prep_xg<<<1024, 256>>>(Wih, bih, bhh);
    lstm_main<<<sms, 1024, SMEM_TOTAL>>>();
    post_rows<<<NACT, 256>>>(actw, rewards);
    post_final<<<1, 256>>>(out);
}